// round 8
// baseline (speedup 1.0000x reference)
#include <cuda_runtime.h>
#include <cuda_bf16.h>
#include <cstdint>
#include <math.h>

// Problem dims (fixed by the reference)
#define TT 4096
#define CC 1024
#define HF 4096
#define NH 16
#define HD 64

// ---------------- scratch (device globals: allocation-free) ----------------
__device__ float g_xn [(size_t)TT * CC];
__device__ float g_y  [(size_t)TT * CC];
__device__ float g_x1 [(size_t)TT * CC];
__device__ float g_h1 [(size_t)TT * HF];
__device__ float g_h3 [(size_t)TT * HF];
// pre-split bf16 Q/K/V (hi + lo residual), Q pre-scaled by log2e/8.
__device__ uint4 g_qh[(size_t)TT * CC / 8];
__device__ uint4 g_ql[(size_t)TT * CC / 8];
__device__ uint4 g_kh[(size_t)TT * CC / 8];
__device__ uint4 g_kl[(size_t)TT * CC / 8];
__device__ uint4 g_vh[(size_t)TT * CC / 8];
__device__ uint4 g_vl[(size_t)TT * CC / 8];

// ================= helpers =================
__device__ __forceinline__ uint32_t smem_u32(const void* p) {
    uint32_t a;
    asm("{ .reg .u64 t; cvta.to.shared.u64 t, %1; cvt.u32.u64 %0, t; }" : "=r"(a) : "l"(p));
    return a;
}
__device__ __forceinline__ uint32_t cvt2(float a, float b) {
    uint32_t r;
    asm("cvt.rn.satfinite.bf16x2.f32 %0, %1, %2;" : "=r"(r) : "f"(b), "f"(a));
    return r;
}
__device__ __forceinline__ float ex2(float x) {
    float r;
    asm("ex2.approx.f32 %0, %1;" : "=f"(r) : "f"(x));
    return r;
}
__device__ __forceinline__ void mma_bf16(float* c, const uint32_t* a, const uint32_t* b) {
    asm volatile(
        "mma.sync.aligned.m16n8k16.row.col.f32.bf16.bf16.f32 "
        "{%0,%1,%2,%3}, {%4,%5,%6,%7}, {%8,%9}, {%0,%1,%2,%3};"
        : "+f"(c[0]), "+f"(c[1]), "+f"(c[2]), "+f"(c[3])
        : "r"(a[0]), "r"(a[1]), "r"(a[2]), "r"(a[3]), "r"(b[0]), "r"(b[1]));
}
__device__ __forceinline__ void ldsm_x4(uint32_t addr, uint32_t& b0, uint32_t& b1,
                                        uint32_t& b2, uint32_t& b3) {
    asm volatile("ldmatrix.sync.aligned.m8n8.x4.shared.b16 {%0,%1,%2,%3}, [%4];"
                 : "=r"(b0), "=r"(b1), "=r"(b2), "=r"(b3) : "r"(addr));
}
__device__ __forceinline__ void ldsm_x4_trans(uint32_t addr, uint32_t& b0, uint32_t& b1,
                                              uint32_t& b2, uint32_t& b3) {
    asm volatile("ldmatrix.sync.aligned.m8n8.x4.trans.shared.b16 {%0,%1,%2,%3}, [%4];"
                 : "=r"(b0), "=r"(b1), "=r"(b2), "=r"(b3) : "r"(addr));
}
__device__ __forceinline__ void split4(float4 v, uint2& h, uint2& l) {
    h.x = cvt2(v.x, v.y);
    h.y = cvt2(v.z, v.w);
    float r0 = v.x - __uint_as_float(h.x << 16);
    float r1 = v.y - __uint_as_float(h.x & 0xFFFF0000u);
    float r2 = v.z - __uint_as_float(h.y << 16);
    float r3 = v.w - __uint_as_float(h.y & 0xFFFF0000u);
    l.x = cvt2(r0, r1);
    l.y = cvt2(r2, r3);
}
__device__ __forceinline__ void cpa16(uint32_t dst, const void* src) {
    asm volatile("cp.async.cg.shared.global [%0], [%1], 16;" :: "r"(dst), "l"(src) : "memory");
}
#define CP_COMMIT() asm volatile("cp.async.commit_group;" ::: "memory")
#define CP_WAIT0()  asm volatile("cp.async.wait_group 0;" ::: "memory")

// ================= bf16-split tensor-core GEMM, ldmatrix fragments ==============
// C[M,N] = op(A)[M,K] * B[N,K]^T (+ add).  ACT: op(A)=silu(A)*A2 elementwise.
// SPLITOUT: write bf16 hi/lo split to q/k/v arrays by column segment, Q pre-scaled.
#define TROW 80
#define TILE_BYTES (128 * TROW)
#define STAGE_BYTES (4 * TILE_BYTES)
#define GEMM_SMEM (2 * STAGE_BYTES)

template<bool ACT, bool SPLITOUT>
__global__ void __launch_bounds__(256)
gemm_bf16s(const float* __restrict__ A, const float* __restrict__ A2,
           const float* __restrict__ B,
           float* __restrict__ C, int M, int N, int K,
           const float* __restrict__ add,
           uint32_t* __restrict__ oqh, uint32_t* __restrict__ oql,
           uint32_t* __restrict__ okh, uint32_t* __restrict__ okl,
           uint32_t* __restrict__ ovh, uint32_t* __restrict__ ovl) {
    extern __shared__ char smem[];
    const uint32_t sbase = smem_u32(smem);

    const int tid  = threadIdx.x;
    const int warp = tid >> 5;
    const int lane = tid & 31;
    const int g = lane >> 2;
    const int t = lane & 3;
    const int blk = lane >> 3, lr = lane & 7;
    const int wm = warp >> 2;
    const int wn = warp & 3;
    const int m0 = wm * 64;
    const int n0 = wn * 32;
    const int bm = blockIdx.y * 128;
    const int bn = blockIdx.x * 128;

    // ldmatrix lane offsets
    const uint32_t aoff = (uint32_t)((blk & 1) * 8 + lr) * TROW + (uint32_t)(blk >> 1) * 16;
    const uint32_t boff = (uint32_t)((lane >> 4) * 8 + lr) * TROW + (uint32_t)(blk & 1) * 16;

    float acc[4][4][4];
    #pragma unroll
    for (int i = 0; i < 4; i++)
        #pragma unroll
        for (int j = 0; j < 4; j++)
            #pragma unroll
            for (int r = 0; r < 4; r++) acc[i][j][r] = 0.f;

    float4 va[4], vb[4];
    const int nc = K >> 5;

    auto loadA = [&](int row, int q, int k0) -> float4 {
        float4 v = *(const float4*)(A + (size_t)(bm + row) * K + k0 + q * 4);
        if (ACT) {
            float4 u = *(const float4*)(A2 + (size_t)(bm + row) * K + k0 + q * 4);
            v.x = v.x / (1.f + __expf(-v.x)) * u.x;
            v.y = v.y / (1.f + __expf(-v.y)) * u.y;
            v.z = v.z / (1.f + __expf(-v.z)) * u.z;
            v.w = v.w / (1.f + __expf(-v.w)) * u.w;
        }
        return v;
    };

    // ---- prologue: load + store chunk 0 (each thread: one A slot AND one B slot per u)
    {
        #pragma unroll
        for (int u = 0; u < 4; u++) {
            int s = tid + u * 256;
            int row = s >> 3, q = s & 7;
            va[u] = loadA(row, q, 0);
            vb[u] = *(const float4*)(B + (size_t)(bn + row) * K + q * 4);
        }
        char* base = smem;
        #pragma unroll
        for (int u = 0; u < 4; u++) {
            int s = tid + u * 256;
            int row = s >> 3, q = s & 7;
            uint32_t off = (uint32_t)row * TROW + (uint32_t)q * 8;
            uint2 h, l;
            split4(va[u], h, l);
            *(uint2*)(base + off)              = h;
            *(uint2*)(base + TILE_BYTES + off) = l;
            split4(vb[u], h, l);
            *(uint2*)(base + 2 * TILE_BYTES + off) = h;
            *(uint2*)(base + 3 * TILE_BYTES + off) = l;
        }
    }
    __syncthreads();

    for (int c = 0; c < nc; c++) {
        const int cur = c & 1;
        const bool more = (c + 1 < nc);

        if (more) {
            int k0 = (c + 1) << 5;
            #pragma unroll
            for (int u = 0; u < 4; u++) {
                int s = tid + u * 256;
                int row = s >> 3, q = s & 7;
                va[u] = loadA(row, q, k0);
                vb[u] = *(const float4*)(B + (size_t)(bn + row) * K + k0 + q * 4);
            }
        }

        // ---- compute on stage cur (ldmatrix fragments)
        {
            const uint32_t stg = sbase + (uint32_t)cur * STAGE_BYTES;

            uint32_t bh[2][2][4], bl[2][2][4];
            #pragma unroll
            for (int j2 = 0; j2 < 2; j2++)
                #pragma unroll
                for (int ks = 0; ks < 2; ks++) {
                    uint32_t ad = stg + 2 * TILE_BYTES +
                                  (uint32_t)(n0 + j2 * 16) * TROW + boff + ks * 32;
                    ldsm_x4(ad, bh[j2][ks][0], bh[j2][ks][1], bh[j2][ks][2], bh[j2][ks][3]);
                    ldsm_x4(ad + TILE_BYTES, bl[j2][ks][0], bl[j2][ks][1], bl[j2][ks][2], bl[j2][ks][3]);
                }

            #pragma unroll
            for (int i = 0; i < 4; i++) {
                uint32_t ad = stg + (uint32_t)(m0 + i * 16) * TROW + aoff;
                uint32_t ah0[4], ah1[4], al0[4], al1[4];
                ldsm_x4(ad,                     ah0[0], ah0[1], ah0[2], ah0[3]);
                ldsm_x4(ad + 32,                ah1[0], ah1[1], ah1[2], ah1[3]);
                ldsm_x4(ad + TILE_BYTES,        al0[0], al0[1], al0[2], al0[3]);
                ldsm_x4(ad + TILE_BYTES + 32,   al1[0], al1[1], al1[2], al1[3]);
                #pragma unroll
                for (int j2 = 0; j2 < 2; j2++)
                    #pragma unroll
                    for (int jj = 0; jj < 2; jj++) {
                        float* cc = acc[i][j2 * 2 + jj];
                        mma_bf16(cc, ah0, &bh[j2][0][jj * 2]);
                        mma_bf16(cc, al0, &bh[j2][0][jj * 2]);
                        mma_bf16(cc, ah0, &bl[j2][0][jj * 2]);
                        mma_bf16(cc, ah1, &bh[j2][1][jj * 2]);
                        mma_bf16(cc, al1, &bh[j2][1][jj * 2]);
                        mma_bf16(cc, ah1, &bl[j2][1][jj * 2]);
                    }
            }
        }

        if (more) {
            char* base = smem + (cur ^ 1) * STAGE_BYTES;
            #pragma unroll
            for (int u = 0; u < 4; u++) {
                int s = tid + u * 256;
                int row = s >> 3, q = s & 7;
                uint32_t off = (uint32_t)row * TROW + (uint32_t)q * 8;
                uint2 h, l;
                split4(va[u], h, l);
                *(uint2*)(base + off)              = h;
                *(uint2*)(base + TILE_BYTES + off) = l;
                split4(vb[u], h, l);
                *(uint2*)(base + 2 * TILE_BYTES + off) = h;
                *(uint2*)(base + 3 * TILE_BYTES + off) = l;
            }
        }
        __syncthreads();
    }

    // ---- epilogue
    if (SPLITOUT) {
        const int seg = bn >> 10;                // 0=Q, 1=K, 2=V
        uint32_t* hp = seg == 0 ? oqh : (seg == 1 ? okh : ovh);
        uint32_t* lp = seg == 0 ? oql : (seg == 1 ? okl : ovl);
        const float sc = (seg == 0) ? 0.18033688011110918f : 1.f;   // log2e/8
        const int cb = (bn & 1023) + n0;
        #pragma unroll
        for (int i = 0; i < 4; i++) {
            size_t r0 = (size_t)(bm + m0 + i * 16 + g);
            size_t r1 = r0 + 8;
            #pragma unroll
            for (int j = 0; j < 4; j++) {
                int cp = (cb + j * 8 + t * 2) >> 1;     // uint32 index in row
                float v0 = acc[i][j][0] * sc, v1 = acc[i][j][1] * sc;
                float v2 = acc[i][j][2] * sc, v3 = acc[i][j][3] * sc;
                uint32_t h0 = cvt2(v0, v1);
                uint32_t l0 = cvt2(v0 - __uint_as_float(h0 << 16),
                                   v1 - __uint_as_float(h0 & 0xFFFF0000u));
                uint32_t h1 = cvt2(v2, v3);
                uint32_t l1 = cvt2(v2 - __uint_as_float(h1 << 16),
                                   v3 - __uint_as_float(h1 & 0xFFFF0000u));
                hp[r0 * 512 + cp] = h0;
                lp[r0 * 512 + cp] = l0;
                hp[r1 * 512 + cp] = h1;
                lp[r1 * 512 + cp] = l1;
            }
        }
    } else {
        #pragma unroll
        for (int i = 0; i < 4; i++) {
            size_t r0 = (size_t)(bm + m0 + i * 16 + g);
            size_t r1 = r0 + 8;
            #pragma unroll
            for (int j = 0; j < 4; j++) {
                int col = bn + n0 + j * 8 + t * 2;
                float2 v0 = make_float2(acc[i][j][0], acc[i][j][1]);
                float2 v1 = make_float2(acc[i][j][2], acc[i][j][3]);
                if (add) {
                    float2 a0 = *(const float2*)(add + r0 * N + col);
                    float2 a1 = *(const float2*)(add + r1 * N + col);
                    v0.x += a0.x; v0.y += a0.y;
                    v1.x += a1.x; v1.y += a1.y;
                }
                *(float2*)(C + r0 * N + col) = v0;
                *(float2*)(C + r1 * N + col) = v1;
            }
        }
    }
}

// ================= MMA flash attention (unchanged — 356us, known good) =========
#define ASTR 144
#define QLSM (128 * ASTR)
#define ABUF0 (2 * QLSM)
#define KVT (64 * ASTR)
#define ABUFB (4 * KVT)
#define ATTN_SMEM (ABUF0 + 2 * ABUFB)  // 110592

__global__ void __launch_bounds__(256, 2)
attn_mma(const char* __restrict__ qhc, const char* __restrict__ qlc,
         const char* __restrict__ khc, const char* __restrict__ klc,
         const char* __restrict__ vhc, const char* __restrict__ vlc,
         float* __restrict__ y) {
    extern __shared__ char sm[];
    const uint32_t sb = smem_u32(sm);
    const int tid  = threadIdx.x;
    const int w    = tid >> 5;
    const int lane = tid & 31;
    const int g = lane >> 2, t = lane & 3;
    const int qt = 31 - (int)blockIdx.x;
    const int h  = blockIdx.y;
    const int q0 = qt * 128;
    const int qko = h * HD;

    const int cr = tid >> 3;
    const int ch = tid & 7;
    const size_t rowb = (size_t)2 * CC;

    #pragma unroll
    for (int u = 0; u < 8; u++) {
        int r = (u & 3) * 32 + cr;
        const char* src = ((u >> 2) ? qlc : qhc) + (size_t)(q0 + r) * rowb + qko * 2 + ch * 16;
        cpa16(sb + (u >> 2) * QLSM + (uint32_t)r * ASTR + ch * 16, src);
    }
    #pragma unroll
    for (int u = 0; u < 8; u++) {
        int r = (u & 1) * 32 + cr;
        const char* tp = (u < 2) ? khc : (u < 4) ? klc : (u < 6) ? vhc : vlc;
        const char* src = tp + (size_t)r * rowb + qko * 2 + ch * 16;
        cpa16(sb + ABUF0 + (u >> 1) * KVT + (uint32_t)r * ASTR + ch * 16, src);
    }
    CP_COMMIT();
    CP_WAIT0();
    __syncthreads();

    const int blk = lane >> 3, lr = lane & 7;
    uint32_t qfh[4][4], qfl[4][4];
    {
        uint32_t qa = sb + (uint32_t)(w * 16 + (blk & 1) * 8 + lr) * ASTR + (uint32_t)(blk >> 1) * 16;
        #pragma unroll
        for (int ks = 0; ks < 4; ks++) {
            ldsm_x4(qa + ks * 32,        qfh[ks][0], qfh[ks][1], qfh[ks][2], qfh[ks][3]);
            ldsm_x4(qa + QLSM + ks * 32, qfl[ks][0], qfl[ks][1], qfl[ks][2], qfl[ks][3]);
        }
    }

    float O[8][4];
    #pragma unroll
    for (int nf = 0; nf < 8; nf++)
        #pragma unroll
        for (int r = 0; r < 4; r++) O[nf][r] = 0.f;
    float l0 = 0.f, l1 = 0.f;

    const int nk = 2 * qt + 2;
    const int r0g = q0 + w * 16 + g;
    const uint32_t ldsmV_off = (uint32_t)((blk & 1) * 8 + lr) * ASTR + (uint32_t)(blk >> 1) * 16;
    const uint32_t ldsmK_off = (uint32_t)(((lane >> 4) << 3) | lr) * ASTR + (uint32_t)((blk & 1) * 16);

    for (int kt = 0; kt < nk; kt++) {
        const uint32_t kb = ABUF0 + (uint32_t)(kt & 1) * ABUFB;
        const bool more = (kt + 1 < nk);

        if (more) {
            int k0n = (kt + 1) * 64;
            uint32_t nb = sb + ABUF0 + (uint32_t)((kt + 1) & 1) * ABUFB;
            #pragma unroll
            for (int u = 0; u < 8; u++) {
                int r = (u & 1) * 32 + cr;
                const char* tp = (u < 2) ? khc : (u < 4) ? klc : (u < 6) ? vhc : vlc;
                const char* src = tp + (size_t)(k0n + r) * rowb + qko * 2 + ch * 16;
                cpa16(nb + (u >> 1) * KVT + (uint32_t)r * ASTR + ch * 16, src);
            }
            CP_COMMIT();
        }

        float S[8][4];
        #pragma unroll
        for (int nf = 0; nf < 8; nf++)
            #pragma unroll
            for (int r = 0; r < 4; r++) S[nf][r] = 0.f;

        {
            const uint32_t kh = sb + kb + ldsmK_off;
            #pragma unroll
            for (int ks = 0; ks < 4; ks++) {
                #pragma unroll
                for (int nfp = 0; nfp < 4; nfp++) {
                    uint32_t a = kh + (uint32_t)(nfp * 16) * ASTR + (uint32_t)(ks * 32);
                    uint32_t h0, h1, h2, h3, l0r, l1r, l2r, l3r;
                    ldsm_x4(a, h0, h1, h2, h3);
                    ldsm_x4(a + KVT, l0r, l1r, l2r, l3r);
                    uint32_t bh0[2] = {h0, h1}, bh1[2] = {h2, h3};
                    uint32_t bl0[2] = {l0r, l1r}, bl1[2] = {l2r, l3r};
                    mma_bf16(S[2 * nfp],     qfh[ks], bh0);
                    mma_bf16(S[2 * nfp],     qfl[ks], bh0);
                    mma_bf16(S[2 * nfp],     qfh[ks], bl0);
                    mma_bf16(S[2 * nfp + 1], qfh[ks], bh1);
                    mma_bf16(S[2 * nfp + 1], qfl[ks], bh1);
                    mma_bf16(S[2 * nfp + 1], qfh[ks], bl1);
                }
            }
        }

        if (kt >= 2 * qt) {
            int k0 = kt * 64;
            #pragma unroll
            for (int nf = 0; nf < 8; nf++) {
                int c = k0 + nf * 8 + 2 * t;
                if (c     > r0g)     S[nf][0] = -1e30f;
                if (c + 1 > r0g)     S[nf][1] = -1e30f;
                if (c     > r0g + 8) S[nf][2] = -1e30f;
                if (c + 1 > r0g + 8) S[nf][3] = -1e30f;
            }
        }

        #pragma unroll
        for (int nf = 0; nf < 8; nf++) {
            S[nf][0] = ex2(S[nf][0]);
            S[nf][1] = ex2(S[nf][1]);
            S[nf][2] = ex2(S[nf][2]);
            S[nf][3] = ex2(S[nf][3]);
            l0 += S[nf][0] + S[nf][1];
            l1 += S[nf][2] + S[nf][3];
        }

        {
            const uint32_t vh = sb + kb + 2 * KVT + ldsmV_off;
            #pragma unroll
            for (int ks = 0; ks < 4; ks++) {
                float p00 = S[2 * ks][0], p01 = S[2 * ks][1];
                float p02 = S[2 * ks][2], p03 = S[2 * ks][3];
                float p10 = S[2 * ks + 1][0], p11 = S[2 * ks + 1][1];
                float p12 = S[2 * ks + 1][2], p13 = S[2 * ks + 1][3];
                uint32_t pah[4], pal[4];
                pah[0] = cvt2(p00, p01);
                pah[1] = cvt2(p02, p03);
                pah[2] = cvt2(p10, p11);
                pah[3] = cvt2(p12, p13);
                pal[0] = cvt2(p00 - __uint_as_float(pah[0] << 16),
                              p01 - __uint_as_float(pah[0] & 0xFFFF0000u));
                pal[1] = cvt2(p02 - __uint_as_float(pah[1] << 16),
                              p03 - __uint_as_float(pah[1] & 0xFFFF0000u));
                pal[2] = cvt2(p10 - __uint_as_float(pah[2] << 16),
                              p11 - __uint_as_float(pah[2] & 0xFFFF0000u));
                pal[3] = cvt2(p12 - __uint_as_float(pah[3] << 16),
                              p13 - __uint_as_float(pah[3] & 0xFFFF0000u));

                uint32_t ka = vh + (uint32_t)(ks * 16) * ASTR;
                #pragma unroll
                for (int np = 0; np < 4; np++) {
                    uint32_t a = ka + (uint32_t)np * 32;
                    uint32_t b0, b1, b2, b3;
                    ldsm_x4_trans(a, b0, b1, b2, b3);
                    uint32_t bb0[2] = {b0, b1}, bb1[2] = {b2, b3};
                    mma_bf16(O[2 * np],     pah, bb0);
                    mma_bf16(O[2 * np + 1], pah, bb1);
                    mma_bf16(O[2 * np],     pal, bb0);
                    mma_bf16(O[2 * np + 1], pal, bb1);
                    ldsm_x4_trans(a + KVT, b0, b1, b2, b3);
                    uint32_t cb0[2] = {b0, b1}, cb1[2] = {b2, b3};
                    mma_bf16(O[2 * np],     pah, cb0);
                    mma_bf16(O[2 * np + 1], pah, cb1);
                }
            }
        }

        if (more) CP_WAIT0();
        __syncthreads();
    }

    l0 += __shfl_xor_sync(0xFFFFFFFFu, l0, 1);
    l0 += __shfl_xor_sync(0xFFFFFFFFu, l0, 2);
    l1 += __shfl_xor_sync(0xFFFFFFFFu, l1, 1);
    l1 += __shfl_xor_sync(0xFFFFFFFFu, l1, 2);
    float i0 = 1.f / l0, i1 = 1.f / l1;
    #pragma unroll
    for (int nf = 0; nf < 8; nf++) {
        int col = qko + nf * 8 + 2 * t;
        *(float2*)(y + (size_t)r0g * CC + col) =
            make_float2(O[nf][0] * i0, O[nf][1] * i0);
        *(float2*)(y + (size_t)(r0g + 8) * CC + col) =
            make_float2(O[nf][2] * i1, O[nf][3] * i1);
    }
}

// ---------------- RMSNorm: one block per row ----------------
__global__ void rmsnorm_kernel(const float* __restrict__ x,
                               const float* __restrict__ w,
                               float* __restrict__ o, int C) {
    int row = blockIdx.x;
    const float* xr = x + (size_t)row * C;
    float s = 0.f;
    for (int i = threadIdx.x; i < C; i += blockDim.x) {
        float v = xr[i];
        s += v * v;
    }
    __shared__ float red[32];
    #pragma unroll
    for (int off = 16; off; off >>= 1) s += __shfl_down_sync(0xFFFFFFFFu, s, off);
    if ((threadIdx.x & 31) == 0) red[threadIdx.x >> 5] = s;
    __syncthreads();
    if (threadIdx.x < 32) {
        float v = (threadIdx.x < (blockDim.x >> 5)) ? red[threadIdx.x] : 0.f;
        #pragma unroll
        for (int off = 16; off; off >>= 1) v += __shfl_down_sync(0xFFFFFFFFu, v, off);
        if (threadIdx.x == 0) red[0] = v;
    }
    __syncthreads();
    float inv = rsqrtf(red[0] / (float)C + 1e-6f);
    for (int i = threadIdx.x; i < C; i += blockDim.x)
        o[(size_t)row * C + i] = xr[i] * inv * w[i];
}

// ---------------- launch ----------------
extern "C" void kernel_launch(void* const* d_in, const int* in_sizes, int n_in,
                              void* d_out, int out_size) {
    const float* x           = (const float*)d_in[0];
    const float* attn_norm_w = (const float*)d_in[1];
    const float* ffn_norm_w  = (const float*)d_in[2];
    const float* c_attn_w    = (const float*)d_in[3];
    const float* c_proj_w    = (const float*)d_in[4];
    const float* w1          = (const float*)d_in[5];
    const float* w2          = (const float*)d_in[6];
    const float* w3          = (const float*)d_in[7];
    float* out = (float*)d_out;

    float *xn, *yb, *x1, *h1, *h3;
    cudaGetSymbolAddress((void**)&xn,  g_xn);
    cudaGetSymbolAddress((void**)&yb,  g_y);
    cudaGetSymbolAddress((void**)&x1,  g_x1);
    cudaGetSymbolAddress((void**)&h1,  g_h1);
    cudaGetSymbolAddress((void**)&h3,  g_h3);
    void *qh, *ql, *kh, *kl, *vh, *vl;
    cudaGetSymbolAddress(&qh, g_qh);
    cudaGetSymbolAddress(&ql, g_ql);
    cudaGetSymbolAddress(&kh, g_kh);
    cudaGetSymbolAddress(&kl, g_kl);
    cudaGetSymbolAddress(&vh, g_vh);
    cudaGetSymbolAddress(&vl, g_vl);

    cudaFuncSetAttribute(gemm_bf16s<false, false>, cudaFuncAttributeMaxDynamicSharedMemorySize, GEMM_SMEM);
    cudaFuncSetAttribute(gemm_bf16s<false, true>,  cudaFuncAttributeMaxDynamicSharedMemorySize, GEMM_SMEM);
    cudaFuncSetAttribute(gemm_bf16s<true, false>,  cudaFuncAttributeMaxDynamicSharedMemorySize, GEMM_SMEM);
    cudaFuncSetAttribute(attn_mma, cudaFuncAttributeMaxDynamicSharedMemorySize, ATTN_SMEM);

    // 1) xn = rmsnorm(x, attn_norm_w)
    rmsnorm_kernel<<<TT, 256>>>(x, attn_norm_w, xn, CC);

    // 2) qkv GEMM with fused bf16 hi/lo split output (Q pre-scaled)
    gemm_bf16s<false, true><<<dim3(3 * CC / 128, TT / 128), 256, GEMM_SMEM>>>(
        xn, nullptr, c_attn_w, nullptr, TT, 3 * CC, CC, nullptr,
        (uint32_t*)qh, (uint32_t*)ql, (uint32_t*)kh, (uint32_t*)kl, (uint32_t*)vh, (uint32_t*)vl);

    // 3) y = causal_attention
    attn_mma<<<dim3(TT / 128, NH), 256, ATTN_SMEM>>>(
        (const char*)qh, (const char*)ql, (const char*)kh,
        (const char*)kl, (const char*)vh, (const char*)vl, yb);

    // 4) x1 = y @ c_proj_w^T + x
    gemm_bf16s<false, false><<<dim3(CC / 128, TT / 128), 256, GEMM_SMEM>>>(
        yb, nullptr, c_proj_w, x1, TT, CC, CC, x,
        nullptr, nullptr, nullptr, nullptr, nullptr, nullptr);

    // 5) xn = rmsnorm(x1, ffn_norm_w)
    rmsnorm_kernel<<<TT, 256>>>(x1, ffn_norm_w, xn, CC);

    // 6) h1 = xn @ w1^T ; h3 = xn @ w3^T
    gemm_bf16s<false, false><<<dim3(HF / 128, TT / 128), 256, GEMM_SMEM>>>(
        xn, nullptr, w1, h1, TT, HF, CC, nullptr,
        nullptr, nullptr, nullptr, nullptr, nullptr, nullptr);
    gemm_bf16s<false, false><<<dim3(HF / 128, TT / 128), 256, GEMM_SMEM>>>(
        xn, nullptr, w3, h3, TT, HF, CC, nullptr,
        nullptr, nullptr, nullptr, nullptr, nullptr, nullptr);

    // 7) out = (silu(h1)*h3) @ w2^T + x1   (swiglu fused into A-load)
    gemm_bf16s<true, false><<<dim3(CC / 128, TT / 128), 256, GEMM_SMEM>>>(
        h1, h3, w2, out, TT, CC, HF, x1,
        nullptr, nullptr, nullptr, nullptr, nullptr, nullptr);
}

// round 9
// speedup vs baseline: 1.5045x; 1.5045x over previous
#include <cuda_runtime.h>
#include <cuda_bf16.h>
#include <cstdint>
#include <math.h>

// Problem dims (fixed by the reference)
#define TT 4096
#define CC 1024
#define HF 4096
#define NH 16
#define HD 64

// ---------------- scratch (device globals: allocation-free) ----------------
__device__ float g_xn [(size_t)TT * CC];
__device__ float g_qkv[(size_t)TT * 3 * CC];
__device__ float g_y  [(size_t)TT * CC];
__device__ float g_x1 [(size_t)TT * CC];
__device__ float g_h1 [(size_t)TT * HF];
__device__ float g_h3 [(size_t)TT * HF];
// pre-split bf16 Q/K/V (hi + lo residual), Q pre-scaled by log2e/8.
__device__ uint4 g_qh[(size_t)TT * CC / 8];
__device__ uint4 g_ql[(size_t)TT * CC / 8];
__device__ uint4 g_kh[(size_t)TT * CC / 8];
__device__ uint4 g_kl[(size_t)TT * CC / 8];
__device__ uint4 g_vh[(size_t)TT * CC / 8];
__device__ uint4 g_vl[(size_t)TT * CC / 8];

// ================= helpers =================
__device__ __forceinline__ uint32_t smem_u32(const void* p) {
    uint32_t a;
    asm("{ .reg .u64 t; cvta.to.shared.u64 t, %1; cvt.u32.u64 %0, t; }" : "=r"(a) : "l"(p));
    return a;
}
__device__ __forceinline__ uint32_t cvt2(float a, float b) {
    uint32_t r;
    asm("cvt.rn.satfinite.bf16x2.f32 %0, %1, %2;" : "=r"(r) : "f"(b), "f"(a));
    return r;
}
__device__ __forceinline__ float ex2(float x) {
    float r;
    asm("ex2.approx.f32 %0, %1;" : "=f"(r) : "f"(x));
    return r;
}
__device__ __forceinline__ void mma_bf16(float* c, const uint32_t* a, const uint32_t* b) {
    asm volatile(
        "mma.sync.aligned.m16n8k16.row.col.f32.bf16.bf16.f32 "
        "{%0,%1,%2,%3}, {%4,%5,%6,%7}, {%8,%9}, {%0,%1,%2,%3};"
        : "+f"(c[0]), "+f"(c[1]), "+f"(c[2]), "+f"(c[3])
        : "r"(a[0]), "r"(a[1]), "r"(a[2]), "r"(a[3]), "r"(b[0]), "r"(b[1]));
}
__device__ __forceinline__ void ldsm_x4(uint32_t addr, uint32_t& b0, uint32_t& b1,
                                        uint32_t& b2, uint32_t& b3) {
    asm volatile("ldmatrix.sync.aligned.m8n8.x4.shared.b16 {%0,%1,%2,%3}, [%4];"
                 : "=r"(b0), "=r"(b1), "=r"(b2), "=r"(b3) : "r"(addr));
}
__device__ __forceinline__ void ldsm_x4_trans(uint32_t addr, uint32_t& b0, uint32_t& b1,
                                              uint32_t& b2, uint32_t& b3) {
    asm volatile("ldmatrix.sync.aligned.m8n8.x4.trans.shared.b16 {%0,%1,%2,%3}, [%4];"
                 : "=r"(b0), "=r"(b1), "=r"(b2), "=r"(b3) : "r"(addr));
}
__device__ __forceinline__ void split4(float4 v, uint2& h, uint2& l) {
    h.x = cvt2(v.x, v.y);
    h.y = cvt2(v.z, v.w);
    float r0 = v.x - __uint_as_float(h.x << 16);
    float r1 = v.y - __uint_as_float(h.x & 0xFFFF0000u);
    float r2 = v.z - __uint_as_float(h.y << 16);
    float r3 = v.w - __uint_as_float(h.y & 0xFFFF0000u);
    l.x = cvt2(r0, r1);
    l.y = cvt2(r2, r3);
}
__device__ __forceinline__ void cpa16(uint32_t dst, const void* src) {
    asm volatile("cp.async.cg.shared.global [%0], [%1], 16;" :: "r"(dst), "l"(src) : "memory");
}
#define CP_COMMIT() asm volatile("cp.async.commit_group;" ::: "memory")
#define CP_WAIT0()  asm volatile("cp.async.wait_group 0;" ::: "memory")

// ================= bf16-split tensor-core GEMM (ldmatrix fragments) ==============
// C[M,N] = A[M,K] * B[N,K]^T (+ add[M,N]), fp32 in/out. 3-term hi/lo split.
#define TROW 80
#define TILE_BYTES (128 * TROW)
#define STAGE_BYTES (4 * TILE_BYTES)
#define GEMM_SMEM (2 * STAGE_BYTES)

__global__ void __launch_bounds__(256)
gemm_bf16s(const float* __restrict__ A, const float* __restrict__ B,
           float* __restrict__ C, int M, int N, int K,
           const float* __restrict__ add) {
    extern __shared__ char smem[];
    const uint32_t sbase = smem_u32(smem);

    const int tid  = threadIdx.x;
    const int warp = tid >> 5;
    const int lane = tid & 31;
    const int g = lane >> 2;
    const int t = lane & 3;
    const int blk = lane >> 3, lr = lane & 7;
    const int wm = warp >> 2;
    const int wn = warp & 3;
    const int m0 = wm * 64;
    const int n0 = wn * 32;
    const int bm = blockIdx.y * 128;
    const int bn = blockIdx.x * 128;

    // ldmatrix lane offsets
    const uint32_t aoff = (uint32_t)((blk & 1) * 8 + lr) * TROW + (uint32_t)(blk >> 1) * 16;
    const uint32_t boff = (uint32_t)((lane >> 4) * 8 + lr) * TROW + (uint32_t)(blk & 1) * 16;

    float acc[4][4][4];
    #pragma unroll
    for (int i = 0; i < 4; i++)
        #pragma unroll
        for (int j = 0; j < 4; j++)
            #pragma unroll
            for (int r = 0; r < 4; r++) acc[i][j][r] = 0.f;

    float4 va[4], vb[4];
    const int nc = K >> 5;

    // ---- prologue: load + store chunk 0
    {
        #pragma unroll
        for (int u = 0; u < 4; u++) {
            int s = tid + u * 256;
            int row = s >> 3, q = s & 7;
            va[u] = *(const float4*)(A + (size_t)(bm + row) * K + q * 4);
            vb[u] = *(const float4*)(B + (size_t)(bn + row) * K + q * 4);
        }
        char* base = smem;
        #pragma unroll
        for (int u = 0; u < 4; u++) {
            int s = tid + u * 256;
            int row = s >> 3, q = s & 7;
            uint32_t off = (uint32_t)row * TROW + (uint32_t)q * 8;
            uint2 h, l;
            split4(va[u], h, l);
            *(uint2*)(base + off)              = h;
            *(uint2*)(base + TILE_BYTES + off) = l;
            split4(vb[u], h, l);
            *(uint2*)(base + 2 * TILE_BYTES + off) = h;
            *(uint2*)(base + 3 * TILE_BYTES + off) = l;
        }
    }
    __syncthreads();

    for (int c = 0; c < nc; c++) {
        const int cur = c & 1;
        const bool more = (c + 1 < nc);

        if (more) {
            int k0 = (c + 1) << 5;
            #pragma unroll
            for (int u = 0; u < 4; u++) {
                int s = tid + u * 256;
                int row = s >> 3, q = s & 7;
                va[u] = *(const float4*)(A + (size_t)(bm + row) * K + k0 + q * 4);
                vb[u] = *(const float4*)(B + (size_t)(bn + row) * K + k0 + q * 4);
            }
        }

        // ---- compute on stage cur (ldmatrix fragments)
        {
            const uint32_t stg = sbase + (uint32_t)cur * STAGE_BYTES;

            uint32_t bh[2][2][4], bl[2][2][4];
            #pragma unroll
            for (int j2 = 0; j2 < 2; j2++)
                #pragma unroll
                for (int ks = 0; ks < 2; ks++) {
                    uint32_t ad = stg + 2 * TILE_BYTES +
                                  (uint32_t)(n0 + j2 * 16) * TROW + boff + ks * 32;
                    ldsm_x4(ad, bh[j2][ks][0], bh[j2][ks][1], bh[j2][ks][2], bh[j2][ks][3]);
                    ldsm_x4(ad + TILE_BYTES, bl[j2][ks][0], bl[j2][ks][1], bl[j2][ks][2], bl[j2][ks][3]);
                }

            #pragma unroll
            for (int i = 0; i < 4; i++) {
                uint32_t ad = stg + (uint32_t)(m0 + i * 16) * TROW + aoff;
                uint32_t ah0[4], ah1[4], al0[4], al1[4];
                ldsm_x4(ad,                     ah0[0], ah0[1], ah0[2], ah0[3]);
                ldsm_x4(ad + 32,                ah1[0], ah1[1], ah1[2], ah1[3]);
                ldsm_x4(ad + TILE_BYTES,        al0[0], al0[1], al0[2], al0[3]);
                ldsm_x4(ad + TILE_BYTES + 32,   al1[0], al1[1], al1[2], al1[3]);
                #pragma unroll
                for (int j2 = 0; j2 < 2; j2++)
                    #pragma unroll
                    for (int jj = 0; jj < 2; jj++) {
                        float* cc = acc[i][j2 * 2 + jj];
                        mma_bf16(cc, ah0, &bh[j2][0][jj * 2]);
                        mma_bf16(cc, al0, &bh[j2][0][jj * 2]);
                        mma_bf16(cc, ah0, &bl[j2][0][jj * 2]);
                        mma_bf16(cc, ah1, &bh[j2][1][jj * 2]);
                        mma_bf16(cc, al1, &bh[j2][1][jj * 2]);
                        mma_bf16(cc, ah1, &bl[j2][1][jj * 2]);
                    }
            }
        }

        if (more) {
            char* base = smem + (cur ^ 1) * STAGE_BYTES;
            #pragma unroll
            for (int u = 0; u < 4; u++) {
                int s = tid + u * 256;
                int row = s >> 3, q = s & 7;
                uint32_t off = (uint32_t)row * TROW + (uint32_t)q * 8;
                uint2 h, l;
                split4(va[u], h, l);
                *(uint2*)(base + off)              = h;
                *(uint2*)(base + TILE_BYTES + off) = l;
                split4(vb[u], h, l);
                *(uint2*)(base + 2 * TILE_BYTES + off) = h;
                *(uint2*)(base + 3 * TILE_BYTES + off) = l;
            }
        }
        __syncthreads();
    }

    // ---- epilogue
    #pragma unroll
    for (int i = 0; i < 4; i++) {
        size_t r0 = (size_t)(bm + m0 + i * 16 + g);
        size_t r1 = r0 + 8;
        #pragma unroll
        for (int j = 0; j < 4; j++) {
            int col = bn + n0 + j * 8 + t * 2;
            float2 v0 = make_float2(acc[i][j][0], acc[i][j][1]);
            float2 v1 = make_float2(acc[i][j][2], acc[i][j][3]);
            if (add) {
                float2 a0 = *(const float2*)(add + r0 * N + col);
                float2 a1 = *(const float2*)(add + r1 * N + col);
                v0.x += a0.x; v0.y += a0.y;
                v1.x += a1.x; v1.y += a1.y;
            }
            *(float2*)(C + r0 * N + col) = v0;
            *(float2*)(C + r1 * N + col) = v1;
        }
    }
}

// ================= QKV pre-split: fp32 qkv -> bf16 hi/lo (Q scaled by log2e/8) =========
__global__ void __launch_bounds__(256)
split_qkv(const float* __restrict__ qkv,
          uint4* __restrict__ qh, uint4* __restrict__ ql,
          uint4* __restrict__ kh, uint4* __restrict__ kl,
          uint4* __restrict__ vh, uint4* __restrict__ vl) {
    const float qs = 1.4426950408889634f * 0.125f;
    int i = blockIdx.x * blockDim.x + threadIdx.x;
    int r  = i >> 7;
    int c8 = (i & 127) * 8;
    const float* base = qkv + (size_t)r * 3 * CC + c8;

    float4 a = *(const float4*)(base);
    float4 b = *(const float4*)(base + 4);
    a.x *= qs; a.y *= qs; a.z *= qs; a.w *= qs;
    b.x *= qs; b.y *= qs; b.z *= qs; b.w *= qs;
    uint2 h0, l0, h1, l1;
    split4(a, h0, l0); split4(b, h1, l1);
    qh[i] = make_uint4(h0.x, h0.y, h1.x, h1.y);
    ql[i] = make_uint4(l0.x, l0.y, l1.x, l1.y);

    a = *(const float4*)(base + CC);
    b = *(const float4*)(base + CC + 4);
    split4(a, h0, l0); split4(b, h1, l1);
    kh[i] = make_uint4(h0.x, h0.y, h1.x, h1.y);
    kl[i] = make_uint4(l0.x, l0.y, l1.x, l1.y);

    a = *(const float4*)(base + 2 * CC);
    b = *(const float4*)(base + 2 * CC + 4);
    split4(a, h0, l0); split4(b, h1, l1);
    vh[i] = make_uint4(h0.x, h0.y, h1.x, h1.y);
    vl[i] = make_uint4(l0.x, l0.y, l1.x, l1.y);
}

// ================= MMA flash attention (unchanged — 356us measured) =========
#define ASTR 144
#define QLSM (128 * ASTR)
#define ABUF0 (2 * QLSM)
#define KVT (64 * ASTR)
#define ABUFB (4 * KVT)
#define ATTN_SMEM (ABUF0 + 2 * ABUFB)  // 110592

__global__ void __launch_bounds__(256, 2)
attn_mma(const char* __restrict__ qhc, const char* __restrict__ qlc,
         const char* __restrict__ khc, const char* __restrict__ klc,
         const char* __restrict__ vhc, const char* __restrict__ vlc,
         float* __restrict__ y) {
    extern __shared__ char sm[];
    const uint32_t sb = smem_u32(sm);
    const int tid  = threadIdx.x;
    const int w    = tid >> 5;
    const int lane = tid & 31;
    const int g = lane >> 2, t = lane & 3;
    const int qt = 31 - (int)blockIdx.x;
    const int h  = blockIdx.y;
    const int q0 = qt * 128;
    const int qko = h * HD;

    const int cr = tid >> 3;
    const int ch = tid & 7;
    const size_t rowb = (size_t)2 * CC;

    #pragma unroll
    for (int u = 0; u < 8; u++) {
        int r = (u & 3) * 32 + cr;
        const char* src = ((u >> 2) ? qlc : qhc) + (size_t)(q0 + r) * rowb + qko * 2 + ch * 16;
        cpa16(sb + (u >> 2) * QLSM + (uint32_t)r * ASTR + ch * 16, src);
    }
    #pragma unroll
    for (int u = 0; u < 8; u++) {
        int r = (u & 1) * 32 + cr;
        const char* tp = (u < 2) ? khc : (u < 4) ? klc : (u < 6) ? vhc : vlc;
        const char* src = tp + (size_t)r * rowb + qko * 2 + ch * 16;
        cpa16(sb + ABUF0 + (u >> 1) * KVT + (uint32_t)r * ASTR + ch * 16, src);
    }
    CP_COMMIT();
    CP_WAIT0();
    __syncthreads();

    const int blk = lane >> 3, lr = lane & 7;
    uint32_t qfh[4][4], qfl[4][4];
    {
        uint32_t qa = sb + (uint32_t)(w * 16 + (blk & 1) * 8 + lr) * ASTR + (uint32_t)(blk >> 1) * 16;
        #pragma unroll
        for (int ks = 0; ks < 4; ks++) {
            ldsm_x4(qa + ks * 32,        qfh[ks][0], qfh[ks][1], qfh[ks][2], qfh[ks][3]);
            ldsm_x4(qa + QLSM + ks * 32, qfl[ks][0], qfl[ks][1], qfl[ks][2], qfl[ks][3]);
        }
    }

    float O[8][4];
    #pragma unroll
    for (int nf = 0; nf < 8; nf++)
        #pragma unroll
        for (int r = 0; r < 4; r++) O[nf][r] = 0.f;
    float l0 = 0.f, l1 = 0.f;

    const int nk = 2 * qt + 2;
    const int r0g = q0 + w * 16 + g;
    const uint32_t ldsmV_off = (uint32_t)((blk & 1) * 8 + lr) * ASTR + (uint32_t)(blk >> 1) * 16;
    const uint32_t ldsmK_off = (uint32_t)(((lane >> 4) << 3) | lr) * ASTR + (uint32_t)((blk & 1) * 16);

    for (int kt = 0; kt < nk; kt++) {
        const uint32_t kb = ABUF0 + (uint32_t)(kt & 1) * ABUFB;
        const bool more = (kt + 1 < nk);

        if (more) {
            int k0n = (kt + 1) * 64;
            uint32_t nb = sb + ABUF0 + (uint32_t)((kt + 1) & 1) * ABUFB;
            #pragma unroll
            for (int u = 0; u < 8; u++) {
                int r = (u & 1) * 32 + cr;
                const char* tp = (u < 2) ? khc : (u < 4) ? klc : (u < 6) ? vhc : vlc;
                const char* src = tp + (size_t)(k0n + r) * rowb + qko * 2 + ch * 16;
                cpa16(nb + (u >> 1) * KVT + (uint32_t)r * ASTR + ch * 16, src);
            }
            CP_COMMIT();
        }

        float S[8][4];
        #pragma unroll
        for (int nf = 0; nf < 8; nf++)
            #pragma unroll
            for (int r = 0; r < 4; r++) S[nf][r] = 0.f;

        {
            const uint32_t kh = sb + kb + ldsmK_off;
            #pragma unroll
            for (int ks = 0; ks < 4; ks++) {
                #pragma unroll
                for (int nfp = 0; nfp < 4; nfp++) {
                    uint32_t a = kh + (uint32_t)(nfp * 16) * ASTR + (uint32_t)(ks * 32);
                    uint32_t h0, h1, h2, h3, l0r, l1r, l2r, l3r;
                    ldsm_x4(a, h0, h1, h2, h3);
                    ldsm_x4(a + KVT, l0r, l1r, l2r, l3r);
                    uint32_t bh0[2] = {h0, h1}, bh1[2] = {h2, h3};
                    uint32_t bl0[2] = {l0r, l1r}, bl1[2] = {l2r, l3r};
                    mma_bf16(S[2 * nfp],     qfh[ks], bh0);
                    mma_bf16(S[2 * nfp],     qfl[ks], bh0);
                    mma_bf16(S[2 * nfp],     qfh[ks], bl0);
                    mma_bf16(S[2 * nfp + 1], qfh[ks], bh1);
                    mma_bf16(S[2 * nfp + 1], qfl[ks], bh1);
                    mma_bf16(S[2 * nfp + 1], qfh[ks], bl1);
                }
            }
        }

        if (kt >= 2 * qt) {
            int k0 = kt * 64;
            #pragma unroll
            for (int nf = 0; nf < 8; nf++) {
                int c = k0 + nf * 8 + 2 * t;
                if (c     > r0g)     S[nf][0] = -1e30f;
                if (c + 1 > r0g)     S[nf][1] = -1e30f;
                if (c     > r0g + 8) S[nf][2] = -1e30f;
                if (c + 1 > r0g + 8) S[nf][3] = -1e30f;
            }
        }

        #pragma unroll
        for (int nf = 0; nf < 8; nf++) {
            S[nf][0] = ex2(S[nf][0]);
            S[nf][1] = ex2(S[nf][1]);
            S[nf][2] = ex2(S[nf][2]);
            S[nf][3] = ex2(S[nf][3]);
            l0 += S[nf][0] + S[nf][1];
            l1 += S[nf][2] + S[nf][3];
        }

        {
            const uint32_t vh = sb + kb + 2 * KVT + ldsmV_off;
            #pragma unroll
            for (int ks = 0; ks < 4; ks++) {
                float p00 = S[2 * ks][0], p01 = S[2 * ks][1];
                float p02 = S[2 * ks][2], p03 = S[2 * ks][3];
                float p10 = S[2 * ks + 1][0], p11 = S[2 * ks + 1][1];
                float p12 = S[2 * ks + 1][2], p13 = S[2 * ks + 1][3];
                uint32_t pah[4], pal[4];
                pah[0] = cvt2(p00, p01);
                pah[1] = cvt2(p02, p03);
                pah[2] = cvt2(p10, p11);
                pah[3] = cvt2(p12, p13);
                pal[0] = cvt2(p00 - __uint_as_float(pah[0] << 16),
                              p01 - __uint_as_float(pah[0] & 0xFFFF0000u));
                pal[1] = cvt2(p02 - __uint_as_float(pah[1] << 16),
                              p03 - __uint_as_float(pah[1] & 0xFFFF0000u));
                pal[2] = cvt2(p10 - __uint_as_float(pah[2] << 16),
                              p11 - __uint_as_float(pah[2] & 0xFFFF0000u));
                pal[3] = cvt2(p12 - __uint_as_float(pah[3] << 16),
                              p13 - __uint_as_float(pah[3] & 0xFFFF0000u));

                uint32_t ka = vh + (uint32_t)(ks * 16) * ASTR;
                #pragma unroll
                for (int np = 0; np < 4; np++) {
                    uint32_t a = ka + (uint32_t)np * 32;
                    uint32_t b0, b1, b2, b3;
                    ldsm_x4_trans(a, b0, b1, b2, b3);
                    uint32_t bb0[2] = {b0, b1}, bb1[2] = {b2, b3};
                    mma_bf16(O[2 * np],     pah, bb0);
                    mma_bf16(O[2 * np + 1], pah, bb1);
                    mma_bf16(O[2 * np],     pal, bb0);
                    mma_bf16(O[2 * np + 1], pal, bb1);
                    ldsm_x4_trans(a + KVT, b0, b1, b2, b3);
                    uint32_t cb0[2] = {b0, b1}, cb1[2] = {b2, b3};
                    mma_bf16(O[2 * np],     pah, cb0);
                    mma_bf16(O[2 * np + 1], pah, cb1);
                }
            }
        }

        if (more) CP_WAIT0();
        __syncthreads();
    }

    l0 += __shfl_xor_sync(0xFFFFFFFFu, l0, 1);
    l0 += __shfl_xor_sync(0xFFFFFFFFu, l0, 2);
    l1 += __shfl_xor_sync(0xFFFFFFFFu, l1, 1);
    l1 += __shfl_xor_sync(0xFFFFFFFFu, l1, 2);
    float i0 = 1.f / l0, i1 = 1.f / l1;
    #pragma unroll
    for (int nf = 0; nf < 8; nf++) {
        int col = qko + nf * 8 + 2 * t;
        *(float2*)(y + (size_t)r0g * CC + col) =
            make_float2(O[nf][0] * i0, O[nf][1] * i0);
        *(float2*)(y + (size_t)(r0g + 8) * CC + col) =
            make_float2(O[nf][2] * i1, O[nf][3] * i1);
    }
}

// ---------------- RMSNorm: one block per row ----------------
__global__ void rmsnorm_kernel(const float* __restrict__ x,
                               const float* __restrict__ w,
                               float* __restrict__ o, int C) {
    int row = blockIdx.x;
    const float* xr = x + (size_t)row * C;
    float s = 0.f;
    for (int i = threadIdx.x; i < C; i += blockDim.x) {
        float v = xr[i];
        s += v * v;
    }
    __shared__ float red[32];
    #pragma unroll
    for (int off = 16; off; off >>= 1) s += __shfl_down_sync(0xFFFFFFFFu, s, off);
    if ((threadIdx.x & 31) == 0) red[threadIdx.x >> 5] = s;
    __syncthreads();
    if (threadIdx.x < 32) {
        float v = (threadIdx.x < (blockDim.x >> 5)) ? red[threadIdx.x] : 0.f;
        #pragma unroll
        for (int off = 16; off; off >>= 1) v += __shfl_down_sync(0xFFFFFFFFu, v, off);
        if (threadIdx.x == 0) red[0] = v;
    }
    __syncthreads();
    float inv = rsqrtf(red[0] / (float)C + 1e-6f);
    for (int i = threadIdx.x; i < C; i += blockDim.x)
        o[(size_t)row * C + i] = xr[i] * inv * w[i];
}

// ---------------- SwiGLU elementwise ----------------
__global__ void swiglu_kernel(float4* __restrict__ h1,
                              const float4* __restrict__ h3, int n4) {
    int i = blockIdx.x * blockDim.x + threadIdx.x;
    if (i < n4) {
        float4 a = h1[i];
        float4 b = h3[i];
        a.x = a.x / (1.f + __expf(-a.x)) * b.x;
        a.y = a.y / (1.f + __expf(-a.y)) * b.y;
        a.z = a.z / (1.f + __expf(-a.z)) * b.z;
        a.w = a.w / (1.f + __expf(-a.w)) * b.w;
        h1[i] = a;
    }
}

// ---------------- launch ----------------
extern "C" void kernel_launch(void* const* d_in, const int* in_sizes, int n_in,
                              void* d_out, int out_size) {
    const float* x           = (const float*)d_in[0];
    const float* attn_norm_w = (const float*)d_in[1];
    const float* ffn_norm_w  = (const float*)d_in[2];
    const float* c_attn_w    = (const float*)d_in[3];
    const float* c_proj_w    = (const float*)d_in[4];
    const float* w1          = (const float*)d_in[5];
    const float* w2          = (const float*)d_in[6];
    const float* w3          = (const float*)d_in[7];
    float* out = (float*)d_out;

    float *xn, *qkv, *yb, *x1, *h1, *h3;
    cudaGetSymbolAddress((void**)&xn,  g_xn);
    cudaGetSymbolAddress((void**)&qkv, g_qkv);
    cudaGetSymbolAddress((void**)&yb,  g_y);
    cudaGetSymbolAddress((void**)&x1,  g_x1);
    cudaGetSymbolAddress((void**)&h1,  g_h1);
    cudaGetSymbolAddress((void**)&h3,  g_h3);
    void *qh, *ql, *kh, *kl, *vh, *vl;
    cudaGetSymbolAddress(&qh, g_qh);
    cudaGetSymbolAddress(&ql, g_ql);
    cudaGetSymbolAddress(&kh, g_kh);
    cudaGetSymbolAddress(&kl, g_kl);
    cudaGetSymbolAddress(&vh, g_vh);
    cudaGetSymbolAddress(&vl, g_vl);

    cudaFuncSetAttribute(gemm_bf16s, cudaFuncAttributeMaxDynamicSharedMemorySize, GEMM_SMEM);
    cudaFuncSetAttribute(attn_mma, cudaFuncAttributeMaxDynamicSharedMemorySize, ATTN_SMEM);

    // 1) xn = rmsnorm(x, attn_norm_w)
    rmsnorm_kernel<<<TT, 256>>>(x, attn_norm_w, xn, CC);

    // 2) qkv = xn @ c_attn_w^T       [4096, 3072]
    gemm_bf16s<<<dim3(3 * CC / 128, TT / 128), 256, GEMM_SMEM>>>(xn, c_attn_w, qkv, TT, 3 * CC, CC, nullptr);

    // 3) pre-split qkv into bf16 hi/lo tensors (Q pre-scaled)
    split_qkv<<<TT * CC / 8 / 256, 256>>>(qkv, (uint4*)qh, (uint4*)ql,
                                          (uint4*)kh, (uint4*)kl, (uint4*)vh, (uint4*)vl);

    // 4) y = causal_attention       [4096, 1024]
    attn_mma<<<dim3(TT / 128, NH), 256, ATTN_SMEM>>>(
        (const char*)qh, (const char*)ql, (const char*)kh,
        (const char*)kl, (const char*)vh, (const char*)vl, yb);

    // 5) x1 = y @ c_proj_w^T + x
    gemm_bf16s<<<dim3(CC / 128, TT / 128), 256, GEMM_SMEM>>>(yb, c_proj_w, x1, TT, CC, CC, x);

    // 6) xn = rmsnorm(x1, ffn_norm_w)
    rmsnorm_kernel<<<TT, 256>>>(x1, ffn_norm_w, xn, CC);

    // 7) h1 = xn @ w1^T ; h3 = xn @ w3^T
    gemm_bf16s<<<dim3(HF / 128, TT / 128), 256, GEMM_SMEM>>>(xn, w1, h1, TT, HF, CC, nullptr);
    gemm_bf16s<<<dim3(HF / 128, TT / 128), 256, GEMM_SMEM>>>(xn, w3, h3, TT, HF, CC, nullptr);

    // 8) h1 = silu(h1) * h3
    {
        int n4 = TT * HF / 4;
        swiglu_kernel<<<n4 / 256, 256>>>((float4*)h1, (const float4*)h3, n4);
    }

    // 9) out = h1 @ w2^T + x1
    gemm_bf16s<<<dim3(CC / 128, TT / 128), 256, GEMM_SMEM>>>(h1, w2, out, TT, CC, HF, x1);
}